// round 10
// baseline (speedup 1.0000x reference)
#include <cuda_runtime.h>
#include <cuda_bf16.h>
#include <cuda_fp16.h>
#include <mma.h>
#include <cstdint>

using namespace nvcuda;

// Shapes: n=8, b=64, h=128, f=256, hs=64
#define N_SEQ 8
#define B_DIM 64
#define H_DIM 128
#define F_DIM 256
#define HS 64
#define M_TOTAL (N_SEQ * B_DIM * H_DIM)   // 65536 rows

// Pre-split fp16 hi/lo Q,K,V (Q pre-scaled by 1/16)
__device__ __half g_Qh[M_TOTAL * HS], g_Ql[M_TOTAL * HS];
__device__ __half g_Kh[M_TOTAL * HS], g_Kl[M_TOTAL * HS];
__device__ __half g_Vh[M_TOTAL * HS], g_Vl[M_TOTAL * HS];

typedef wmma::fragment<wmma::matrix_a, 16, 16, 16, __nv_bfloat16, wmma::row_major> FragA;
typedef wmma::fragment<wmma::matrix_b, 16, 16, 16, __nv_bfloat16, wmma::row_major> FragB;
typedef wmma::fragment<wmma::accumulator, 16, 16, 16, float> FragC;

__device__ __forceinline__ void split2(float x, __nv_bfloat16& h, __nv_bfloat16& l) {
    h = __float2bfloat16(x);
    l = __float2bfloat16(x - __bfloat162float(h));
}
__device__ __forceinline__ void split2h(float x, __half& h, __half& l) {
    h = __float2half(x);
    l = __float2half(x - __half2float(h));
}

__device__ __forceinline__ uint32_t smem_u32(const void* p) {
    uint32_t a;
    asm("{ .reg .u64 t; cvta.to.shared.u64 t, %1; cvt.u32.u64 %0, t; }" : "=r"(a) : "l"(p));
    return a;
}

// fp16 mma, f32 accumulate
__device__ __forceinline__ void mma16816(float* c, const uint32_t* a,
                                         uint32_t b0, uint32_t b1) {
    asm volatile(
        "mma.sync.aligned.m16n8k16.row.col.f32.f16.f16.f32 "
        "{%0,%1,%2,%3},{%4,%5,%6,%7},{%8,%9},{%0,%1,%2,%3};"
        : "+f"(c[0]), "+f"(c[1]), "+f"(c[2]), "+f"(c[3])
        : "r"(a[0]), "r"(a[1]), "r"(a[2]), "r"(a[3]), "r"(b0), "r"(b1));
}
// fp16 mma, f16 accumulate (cross-term passes) — D/C = 2 regs of f16x2,
// cell mapping identical to f32 accum: reg0 = (c0,c1), reg1 = (c2,c3).
__device__ __forceinline__ void mma16816h(uint32_t* c, const uint32_t* a,
                                          uint32_t b0, uint32_t b1) {
    asm volatile(
        "mma.sync.aligned.m16n8k16.row.col.f16.f16.f16.f16 "
        "{%0,%1},{%2,%3,%4,%5},{%6,%7},{%0,%1};"
        : "+r"(c[0]), "+r"(c[1])
        : "r"(a[0]), "r"(a[1]), "r"(a[2]), "r"(a[3]), "r"(b0), "r"(b1));
}
__device__ __forceinline__ void ldsm4(uint32_t& r0, uint32_t& r1, uint32_t& r2,
                                      uint32_t& r3, uint32_t addr) {
    asm volatile("ldmatrix.sync.aligned.m8n8.x4.shared.b16 {%0,%1,%2,%3}, [%4];"
                 : "=r"(r0), "=r"(r1), "=r"(r2), "=r"(r3) : "r"(addr));
}
__device__ __forceinline__ void ldsm4t(uint32_t& r0, uint32_t& r1, uint32_t& r2,
                                       uint32_t& r3, uint32_t addr) {
    asm volatile("ldmatrix.sync.aligned.m8n8.x4.trans.shared.b16 {%0,%1,%2,%3}, [%4];"
                 : "=r"(r0), "=r"(r1), "=r"(r2), "=r"(r3) : "r"(addr));
}

// ---------------------------------------------------------------------------
// Kernel A: QKV via bf16 wmma split-3 (unchanged internals), epilogue now
// emits PRE-SPLIT fp16 hi/lo. grid (1024,3), block 256. Warps 4M x 2N.
// ---------------------------------------------------------------------------
#define XSTR 40
#define WSTR 72

__global__ __launch_bounds__(256) void qkv_kernel(
    const float* __restrict__ x,
    const float* __restrict__ Wq,
    const float* __restrict__ Wk,
    const float* __restrict__ Wv)
{
    __shared__ __nv_bfloat16 xs_hi[64][XSTR], xs_lo[64][XSTR];
    __shared__ __nv_bfloat16 ws_hi[32][WSTR], ws_lo[32][WSTR];
    __shared__ float sbuf[8][16 * 20];

    const int t    = threadIdx.x;
    const int w    = t >> 5;
    const int lane = t & 31;
    const int wm   = w >> 1;
    const int wn   = w & 1;
    const int rowBase = blockIdx.x * 64;
    const int which = blockIdx.y;
    const float* __restrict__ W = (which == 0) ? Wq : (which == 1) ? Wk : Wv;
    __half* __restrict__ outH = (which == 0) ? g_Qh : (which == 1) ? g_Kh : g_Vh;
    __half* __restrict__ outL = (which == 0) ? g_Ql : (which == 1) ? g_Kl : g_Vl;
    const float inScale = (which == 0) ? 0.0625f : 1.0f;

    FragC acc[2];
    wmma::fill_fragment(acc[0], 0.0f);
    wmma::fill_fragment(acc[1], 0.0f);

    for (int k0 = 0; k0 < F_DIM; k0 += 32) {
#pragma unroll
        for (int p = 0; p < 2; p++) {   // x tile 64x32
            int e = t + p * 256;
            int row = e >> 3;
            int lc  = (e & 7) * 4;
            float4 v = *(const float4*)&x[(size_t)(rowBase + row) * F_DIM + k0 + lc];
            v.x *= inScale; v.y *= inScale; v.z *= inScale; v.w *= inScale;
            __nv_bfloat16 h0,l0,h1,l1,h2,l2,h3,l3;
            split2(v.x,h0,l0); split2(v.y,h1,l1); split2(v.z,h2,l2); split2(v.w,h3,l3);
            *(__nv_bfloat162*)&xs_hi[row][lc]     = __nv_bfloat162(h0, h1);
            *(__nv_bfloat162*)&xs_hi[row][lc + 2] = __nv_bfloat162(h2, h3);
            *(__nv_bfloat162*)&xs_lo[row][lc]     = __nv_bfloat162(l0, l1);
            *(__nv_bfloat162*)&xs_lo[row][lc + 2] = __nv_bfloat162(l2, l3);
        }
#pragma unroll
        for (int p = 0; p < 2; p++) {   // W chunk 32x64
            int e = t + p * 256;
            int k  = e >> 4;
            int cg = (e & 15) * 4;
            float4 v = *(const float4*)&W[(size_t)(k0 + k) * HS + cg];
            __nv_bfloat16 h0,l0,h1,l1,h2,l2,h3,l3;
            split2(v.x,h0,l0); split2(v.y,h1,l1); split2(v.z,h2,l2); split2(v.w,h3,l3);
            *(__nv_bfloat162*)&ws_hi[k][cg]     = __nv_bfloat162(h0, h1);
            *(__nv_bfloat162*)&ws_hi[k][cg + 2] = __nv_bfloat162(h2, h3);
            *(__nv_bfloat162*)&ws_lo[k][cg]     = __nv_bfloat162(l0, l1);
            *(__nv_bfloat162*)&ws_lo[k][cg + 2] = __nv_bfloat162(l2, l3);
        }
        __syncthreads();

#pragma unroll
        for (int kk = 0; kk < 32; kk += 16) {
            FragA a_hi, a_lo;
            wmma::load_matrix_sync(a_hi, &xs_hi[wm * 16][kk], XSTR);
            wmma::load_matrix_sync(a_lo, &xs_lo[wm * 16][kk], XSTR);
#pragma unroll
            for (int nt = 0; nt < 2; nt++) {
                FragB b_hi, b_lo;
                wmma::load_matrix_sync(b_hi, &ws_hi[kk][wn * 32 + nt * 16], WSTR);
                wmma::load_matrix_sync(b_lo, &ws_lo[kk][wn * 32 + nt * 16], WSTR);
                wmma::mma_sync(acc[nt], a_hi, b_hi, acc[nt]);
                wmma::mma_sync(acc[nt], a_hi, b_lo, acc[nt]);
                wmma::mma_sync(acc[nt], a_lo, b_hi, acc[nt]);
            }
        }
        __syncthreads();
    }

#pragma unroll
    for (int nt = 0; nt < 2; nt++) {
        wmma::store_matrix_sync(&sbuf[w][0], acc[nt], 20, wmma::mem_row_major);
        __syncwarp();
        int r  = lane & 15;
        int cg = (lane >> 4) * 8;
        size_t gbase = (size_t)(rowBase + wm * 16 + r) * HS + wn * 32 + nt * 16 + cg;
        __half hh[8], ll[8];
#pragma unroll
        for (int c = 0; c < 8; c++)
            split2h(sbuf[w][r * 20 + cg + c], hh[c], ll[c]);
#pragma unroll
        for (int c = 0; c < 8; c += 2) {
            *(__half2*)&outH[gbase + c] = __halves2half2(hh[c], hh[c + 1]);
            *(__half2*)&outL[gbase + c] = __halves2half2(ll[c], ll[c + 1]);
        }
        __syncwarp();
    }
}

// ---------------------------------------------------------------------------
// Kernel B: FA-style attention, fp16 mma. Main pass f32-accum; BOTH cross
// passes accumulate into ONE f16 accumulator (testing 2x f16-accum rate),
// merged into the f32 accumulators with FADDs.
// grid 1024 = (j,b,half), block 128 (4 warps). K/V smem stride 72.
// ---------------------------------------------------------------------------
#define KVS 72   // fp16 elements per row

__global__ __launch_bounds__(128) void attn_kernel(float* __restrict__ out)
{
    extern __shared__ __half sm[];
    __half* kh = sm;
    __half* kl = kh + 128 * KVS;
    __half* vh = kl + 128 * KVS;
    __half* vl = vh + 128 * KVS;

    const int t    = threadIdx.x;
    const int w    = t >> 5;
    const int lane = t & 31;
    const int g    = lane >> 2;
    const int tg   = lane & 3;
    const int j    = blockIdx.x & 7;
    const int b    = (blockIdx.x >> 3) & 63;
    const int half_ = blockIdx.x >> 9;
    const int qrow = (j * B_DIM + b) * H_DIM + half_ * 64;

    const uint32_t khb = smem_u32(kh), klb = smem_u32(kl);
    const uint32_t vhb = smem_u32(vh), vlb = smem_u32(vl);

    // lane-invariant ldmatrix offsets (bytes)
    const uint32_t aofs  = (uint32_t)(((lane & 15) * KVS + ((lane >> 4) << 3)) * 2);
    const uint32_t kmofs = (uint32_t)((((lane & 7) + ((lane >> 4) << 3)) * KVS
                                       + (((lane >> 3) & 1) << 3)) * 2);
    const uint32_t vmofs = (uint32_t)((((lane & 7) + (((lane >> 3) & 1) << 3)) * KVS
                                       + ((lane >> 4) << 3)) * 2);

    // ---- stage Q (64 rows) into vh/vl, hoist A-frags to registers ----
#pragma unroll
    for (int p = 0; p < 8; p++) {
        int e = t + p * 128;
        int arr = e >> 9;
        int idx = e & 511;
        int row = idx >> 3;
        int ch  = idx & 7;
        const __half* src = arr ? g_Ql : g_Qh;
        __half* dst = arr ? vl : vh;
        *(uint4*)&dst[row * KVS + ch * 8] =
            *(const uint4*)&src[(size_t)(qrow + row) * HS + ch * 8];
    }
    __syncthreads();

    uint32_t qhf[4][4], qlf[4][4];
#pragma unroll
    for (int ks = 0; ks < 4; ks++) {
        uint32_t off = (uint32_t)((w * 16 * KVS + ks * 16) * 2);
        ldsm4(qhf[ks][0], qhf[ks][1], qhf[ks][2], qhf[ks][3], vhb + off + aofs);
        ldsm4(qlf[ks][0], qlf[ks][1], qlf[ks][2], qlf[ks][3], vlb + off + aofs);
    }

    float oacc[8][4];
#pragma unroll
    for (int nf = 0; nf < 8; nf++)
#pragma unroll
        for (int c = 0; c < 4; c++) oacc[nf][c] = 0.f;

    for (int i = 0; i < N_SEQ; i++) {
        __syncthreads();   // prev PV reads done (and Q-frag loads at i==0)
        const int kb0 = (i * B_DIM + b) * H_DIM;
#pragma unroll 8
        for (int p = 0; p < 32; p++) {
            int e = t + p * 128;
            int arr = e >> 10;
            int idx = e & 1023;
            int row = idx >> 3;
            int ch  = idx & 7;
            const __half* src = (arr == 0) ? g_Kh : (arr == 1) ? g_Kl
                               : (arr == 2) ? g_Vh : g_Vl;
            __half* dst = (arr == 0) ? kh : (arr == 1) ? kl
                         : (arr == 2) ? vh : vl;
            *(uint4*)&dst[row * KVS + ch * 8] =
                *(const uint4*)&src[(size_t)(kb0 + row) * HS + ch * 8];
        }
        __syncthreads();

        // ---- S = Q K^T : main pass f32-accum, cross passes f16-accum ----
        float sacc[16][4];
        uint32_t xacc[16][2];
#pragma unroll
        for (int nf = 0; nf < 16; nf++) {
#pragma unroll
            for (int c = 0; c < 4; c++) sacc[nf][c] = 0.f;
            xacc[nf][0] = 0u; xacc[nf][1] = 0u;
        }

#pragma unroll
        for (int ks = 0; ks < 4; ks++) {
#pragma unroll
            for (int nfp = 0; nfp < 8; nfp++) {
                uint32_t off = (uint32_t)((nfp * 16 * KVS + ks * 16) * 2);
                uint32_t bh0, bh1, bh2, bh3, bl0, bl1, bl2, bl3;
                ldsm4(bh0, bh1, bh2, bh3, khb + off + kmofs);
                ldsm4(bl0, bl1, bl2, bl3, klb + off + kmofs);
                mma16816(sacc[2 * nfp],      qhf[ks], bh0, bh1);
                mma16816(sacc[2 * nfp + 1],  qhf[ks], bh2, bh3);
                mma16816h(xacc[2 * nfp],     qhf[ks], bl0, bl1);
                mma16816h(xacc[2 * nfp],     qlf[ks], bh0, bh1);
                mma16816h(xacc[2 * nfp + 1], qhf[ks], bl2, bl3);
                mma16816h(xacc[2 * nfp + 1], qlf[ks], bh2, bh3);
            }
        }
        // merge f16 cross into f32
#pragma unroll
        for (int nf = 0; nf < 16; nf++) {
            __half2 x01 = *(__half2*)&xacc[nf][0];
            __half2 x23 = *(__half2*)&xacc[nf][1];
            sacc[nf][0] += __low2float(x01);
            sacc[nf][1] += __high2float(x01);
            sacc[nf][2] += __low2float(x23);
            sacc[nf][3] += __high2float(x23);
        }

        // ---- softmax in registers ----
        float mx_a = sacc[0][0], mx_b = sacc[0][2];
#pragma unroll
        for (int nf = 0; nf < 16; nf++) {
            mx_a = fmaxf(mx_a, fmaxf(sacc[nf][0], sacc[nf][1]));
            mx_b = fmaxf(mx_b, fmaxf(sacc[nf][2], sacc[nf][3]));
        }
        mx_a = fmaxf(mx_a, __shfl_xor_sync(0xffffffffu, mx_a, 1));
        mx_a = fmaxf(mx_a, __shfl_xor_sync(0xffffffffu, mx_a, 2));
        mx_b = fmaxf(mx_b, __shfl_xor_sync(0xffffffffu, mx_b, 1));
        mx_b = fmaxf(mx_b, __shfl_xor_sync(0xffffffffu, mx_b, 2));
        float sum_a = 0.f, sum_b = 0.f;
#pragma unroll
        for (int nf = 0; nf < 16; nf++) {
            sacc[nf][0] = __expf(sacc[nf][0] - mx_a);
            sacc[nf][1] = __expf(sacc[nf][1] - mx_a);
            sacc[nf][2] = __expf(sacc[nf][2] - mx_b);
            sacc[nf][3] = __expf(sacc[nf][3] - mx_b);
            sum_a += sacc[nf][0] + sacc[nf][1];
            sum_b += sacc[nf][2] + sacc[nf][3];
        }
        sum_a += __shfl_xor_sync(0xffffffffu, sum_a, 1);
        sum_a += __shfl_xor_sync(0xffffffffu, sum_a, 2);
        sum_b += __shfl_xor_sync(0xffffffffu, sum_b, 1);
        sum_b += __shfl_xor_sync(0xffffffffu, sum_b, 2);
        const float inv_a = 1.0f / sum_a, inv_b = 1.0f / sum_b;

        // ---- pack P (fp16 hi/lo) into A-fragment registers ----
        uint32_t pah[8][4], pal[8][4];
#pragma unroll
        for (int s = 0; s < 8; s++) {
#pragma unroll
            for (int hf = 0; hf < 2; hf++) {
                int nf = 2 * s + hf;
                float p0 = sacc[nf][0] * inv_a, p1 = sacc[nf][1] * inv_a;
                float p2 = sacc[nf][2] * inv_b, p3 = sacc[nf][3] * inv_b;
                __half h0,l0,h1,l1,h2,l2,h3,l3;
                split2h(p0,h0,l0); split2h(p1,h1,l1);
                split2h(p2,h2,l2); split2h(p3,h3,l3);
                __half2 ph01 = __halves2half2(h0,h1), ph23 = __halves2half2(h2,h3);
                __half2 pl01 = __halves2half2(l0,l1), pl23 = __halves2half2(l2,l3);
                pah[s][2 * hf]     = *(uint32_t*)&ph01;
                pah[s][2 * hf + 1] = *(uint32_t*)&ph23;
                pal[s][2 * hf]     = *(uint32_t*)&pl01;
                pal[s][2 * hf + 1] = *(uint32_t*)&pl23;
            }
        }

        // ---- O += P V : main f32-accum, cross f16-accum (merged per i) ----
        uint32_t ox[8][2];
#pragma unroll
        for (int nf = 0; nf < 8; nf++) { ox[nf][0] = 0u; ox[nf][1] = 0u; }

#pragma unroll
        for (int s = 0; s < 8; s++) {
#pragma unroll
            for (int nfp = 0; nfp < 4; nfp++) {
                uint32_t off = (uint32_t)((s * 16 * KVS + nfp * 16) * 2);
                uint32_t bh0, bh1, bh2, bh3, bl0, bl1, bl2, bl3;
                ldsm4t(bh0, bh1, bh2, bh3, vhb + off + vmofs);
                ldsm4t(bl0, bl1, bl2, bl3, vlb + off + vmofs);
                mma16816(oacc[2 * nfp],      pah[s], bh0, bh1);
                mma16816(oacc[2 * nfp + 1],  pah[s], bh2, bh3);
                mma16816h(ox[2 * nfp],       pah[s], bl0, bl1);
                mma16816h(ox[2 * nfp],       pal[s], bh0, bh1);
                mma16816h(ox[2 * nfp + 1],   pah[s], bl2, bl3);
                mma16816h(ox[2 * nfp + 1],   pal[s], bh2, bh3);
            }
        }
#pragma unroll
        for (int nf = 0; nf < 8; nf++) {
            __half2 x01 = *(__half2*)&ox[nf][0];
            __half2 x23 = *(__half2*)&ox[nf][1];
            oacc[nf][0] += __low2float(x01);
            oacc[nf][1] += __high2float(x01);
            oacc[nf][2] += __low2float(x23);
            oacc[nf][3] += __high2float(x23);
        }
    }

    // ---- write O ----
#pragma unroll
    for (int nf = 0; nf < 8; nf++) {
        size_t r0 = (size_t)(qrow + w * 16 + g) * HS + nf * 8 + 2 * tg;
        size_t r1 = (size_t)(qrow + w * 16 + g + 8) * HS + nf * 8 + 2 * tg;
        *(float2*)&out[r0] = make_float2(oacc[nf][0], oacc[nf][1]);
        *(float2*)&out[r1] = make_float2(oacc[nf][2], oacc[nf][3]);
    }
}

// ---------------------------------------------------------------------------
extern "C" void kernel_launch(void* const* d_in, const int* in_sizes, int n_in,
                              void* d_out, int out_size)
{
    const float* x  = (const float*)d_in[0];
    const float* Wq = (const float*)d_in[1];
    const float* Wk = (const float*)d_in[2];
    const float* Wv = (const float*)d_in[3];
    float* out = (float*)d_out;

    qkv_kernel<<<dim3(1024, 3), 256>>>(x, Wq, Wk, Wv);

    int smemB = 4 * 128 * KVS * (int)sizeof(__half);   // 73728
    cudaFuncSetAttribute(attn_kernel, cudaFuncAttributeMaxDynamicSharedMemorySize, smemB);
    attn_kernel<<<1024, 128, smemB>>>(out);
}

// round 11
// speedup vs baseline: 1.8614x; 1.8614x over previous
#include <cuda_runtime.h>
#include <cuda_bf16.h>
#include <cuda_fp16.h>
#include <mma.h>
#include <cstdint>

using namespace nvcuda;

// Shapes: n=8, b=64, h=128, f=256, hs=64
#define N_SEQ 8
#define B_DIM 64
#define H_DIM 128
#define F_DIM 256
#define HS 64
#define M_TOTAL (N_SEQ * B_DIM * H_DIM)   // 65536 rows

// Pre-split fp16 hi/lo Q,K (Q pre-scaled by 1/16); V needs hi only (PV is
// single-pass) but qkv's shared epilogue writes both.
__device__ __half g_Qh[M_TOTAL * HS], g_Ql[M_TOTAL * HS];
__device__ __half g_Kh[M_TOTAL * HS], g_Kl[M_TOTAL * HS];
__device__ __half g_Vh[M_TOTAL * HS], g_Vl[M_TOTAL * HS];

typedef wmma::fragment<wmma::matrix_a, 16, 16, 16, __nv_bfloat16, wmma::row_major> FragA;
typedef wmma::fragment<wmma::matrix_b, 16, 16, 16, __nv_bfloat16, wmma::row_major> FragB;
typedef wmma::fragment<wmma::accumulator, 16, 16, 16, float> FragC;

__device__ __forceinline__ void split2(float x, __nv_bfloat16& h, __nv_bfloat16& l) {
    h = __float2bfloat16(x);
    l = __float2bfloat16(x - __bfloat162float(h));
}
__device__ __forceinline__ void split2h(float x, __half& h, __half& l) {
    h = __float2half(x);
    l = __float2half(x - __half2float(h));
}

__device__ __forceinline__ uint32_t smem_u32(const void* p) {
    uint32_t a;
    asm("{ .reg .u64 t; cvta.to.shared.u64 t, %1; cvt.u32.u64 %0, t; }" : "=r"(a) : "l"(p));
    return a;
}

// fp16 mma, f32 accumulate
__device__ __forceinline__ void mma16816(float* c, const uint32_t* a,
                                         uint32_t b0, uint32_t b1) {
    asm volatile(
        "mma.sync.aligned.m16n8k16.row.col.f32.f16.f16.f32 "
        "{%0,%1,%2,%3},{%4,%5,%6,%7},{%8,%9},{%0,%1,%2,%3};"
        : "+f"(c[0]), "+f"(c[1]), "+f"(c[2]), "+f"(c[3])
        : "r"(a[0]), "r"(a[1]), "r"(a[2]), "r"(a[3]), "r"(b0), "r"(b1));
}
__device__ __forceinline__ void ldsm4(uint32_t& r0, uint32_t& r1, uint32_t& r2,
                                      uint32_t& r3, uint32_t addr) {
    asm volatile("ldmatrix.sync.aligned.m8n8.x4.shared.b16 {%0,%1,%2,%3}, [%4];"
                 : "=r"(r0), "=r"(r1), "=r"(r2), "=r"(r3) : "r"(addr));
}
__device__ __forceinline__ void ldsm4t(uint32_t& r0, uint32_t& r1, uint32_t& r2,
                                       uint32_t& r3, uint32_t addr) {
    asm volatile("ldmatrix.sync.aligned.m8n8.x4.trans.shared.b16 {%0,%1,%2,%3}, [%4];"
                 : "=r"(r0), "=r"(r1), "=r"(r2), "=r"(r3) : "r"(addr));
}

// ---------------------------------------------------------------------------
// Kernel A: QKV via bf16 wmma split-3 (proven), epilogue emits fp16 hi/lo.
// grid (1024,3), block 256. Per CTA 64 rows x 64 cols. Warps 4M x 2N.
// ---------------------------------------------------------------------------
#define XSTR 40
#define WSTR 72

__global__ __launch_bounds__(256) void qkv_kernel(
    const float* __restrict__ x,
    const float* __restrict__ Wq,
    const float* __restrict__ Wk,
    const float* __restrict__ Wv)
{
    __shared__ __nv_bfloat16 xs_hi[64][XSTR], xs_lo[64][XSTR];
    __shared__ __nv_bfloat16 ws_hi[32][WSTR], ws_lo[32][WSTR];
    __shared__ float sbuf[8][16 * 20];

    const int t    = threadIdx.x;
    const int w    = t >> 5;
    const int lane = t & 31;
    const int wm   = w >> 1;
    const int wn   = w & 1;
    const int rowBase = blockIdx.x * 64;
    const int which = blockIdx.y;
    const float* __restrict__ W = (which == 0) ? Wq : (which == 1) ? Wk : Wv;
    __half* __restrict__ outH = (which == 0) ? g_Qh : (which == 1) ? g_Kh : g_Vh;
    __half* __restrict__ outL = (which == 0) ? g_Ql : (which == 1) ? g_Kl : g_Vl;
    const float inScale = (which == 0) ? 0.0625f : 1.0f;

    FragC acc[2];
    wmma::fill_fragment(acc[0], 0.0f);
    wmma::fill_fragment(acc[1], 0.0f);

    for (int k0 = 0; k0 < F_DIM; k0 += 32) {
#pragma unroll
        for (int p = 0; p < 2; p++) {   // x tile 64x32
            int e = t + p * 256;
            int row = e >> 3;
            int lc  = (e & 7) * 4;
            float4 v = *(const float4*)&x[(size_t)(rowBase + row) * F_DIM + k0 + lc];
            v.x *= inScale; v.y *= inScale; v.z *= inScale; v.w *= inScale;
            __nv_bfloat16 h0,l0,h1,l1,h2,l2,h3,l3;
            split2(v.x,h0,l0); split2(v.y,h1,l1); split2(v.z,h2,l2); split2(v.w,h3,l3);
            *(__nv_bfloat162*)&xs_hi[row][lc]     = __nv_bfloat162(h0, h1);
            *(__nv_bfloat162*)&xs_hi[row][lc + 2] = __nv_bfloat162(h2, h3);
            *(__nv_bfloat162*)&xs_lo[row][lc]     = __nv_bfloat162(l0, l1);
            *(__nv_bfloat162*)&xs_lo[row][lc + 2] = __nv_bfloat162(l2, l3);
        }
#pragma unroll
        for (int p = 0; p < 2; p++) {   // W chunk 32x64
            int e = t + p * 256;
            int k  = e >> 4;
            int cg = (e & 15) * 4;
            float4 v = *(const float4*)&W[(size_t)(k0 + k) * HS + cg];
            __nv_bfloat16 h0,l0,h1,l1,h2,l2,h3,l3;
            split2(v.x,h0,l0); split2(v.y,h1,l1); split2(v.z,h2,l2); split2(v.w,h3,l3);
            *(__nv_bfloat162*)&ws_hi[k][cg]     = __nv_bfloat162(h0, h1);
            *(__nv_bfloat162*)&ws_hi[k][cg + 2] = __nv_bfloat162(h2, h3);
            *(__nv_bfloat162*)&ws_lo[k][cg]     = __nv_bfloat162(l0, l1);
            *(__nv_bfloat162*)&ws_lo[k][cg + 2] = __nv_bfloat162(l2, l3);
        }
        __syncthreads();

#pragma unroll
        for (int kk = 0; kk < 32; kk += 16) {
            FragA a_hi, a_lo;
            wmma::load_matrix_sync(a_hi, &xs_hi[wm * 16][kk], XSTR);
            wmma::load_matrix_sync(a_lo, &xs_lo[wm * 16][kk], XSTR);
#pragma unroll
            for (int nt = 0; nt < 2; nt++) {
                FragB b_hi, b_lo;
                wmma::load_matrix_sync(b_hi, &ws_hi[kk][wn * 32 + nt * 16], WSTR);
                wmma::load_matrix_sync(b_lo, &ws_lo[kk][wn * 32 + nt * 16], WSTR);
                wmma::mma_sync(acc[nt], a_hi, b_hi, acc[nt]);
                wmma::mma_sync(acc[nt], a_hi, b_lo, acc[nt]);
                wmma::mma_sync(acc[nt], a_lo, b_hi, acc[nt]);
            }
        }
        __syncthreads();
    }

#pragma unroll
    for (int nt = 0; nt < 2; nt++) {
        wmma::store_matrix_sync(&sbuf[w][0], acc[nt], 20, wmma::mem_row_major);
        __syncwarp();
        int r  = lane & 15;
        int cg = (lane >> 4) * 8;
        size_t gbase = (size_t)(rowBase + wm * 16 + r) * HS + wn * 32 + nt * 16 + cg;
        __half hh[8], ll[8];
#pragma unroll
        for (int c = 0; c < 8; c++)
            split2h(sbuf[w][r * 20 + cg + c], hh[c], ll[c]);
#pragma unroll
        for (int c = 0; c < 8; c += 2) {
            *(__half2*)&outH[gbase + c] = __halves2half2(hh[c], hh[c + 1]);
            *(__half2*)&outL[gbase + c] = __halves2half2(ll[c], ll[c + 1]);
        }
        __syncwarp();
    }
}

// ---------------------------------------------------------------------------
// Kernel B: FA-style attention, fp16 mma f32-accum.
// S = QK^T split-3 (accuracy-critical: exponentiated).
// O += P V SINGLE-PASS (Ph·Vh): error enters linearly, ~3.4e-4.
// grid 1024 = (j,b,half), block 128 (4 warps). K hi/lo + V hi in smem (str 72).
// ---------------------------------------------------------------------------
#define KVS 72   // fp16 elements per row

__global__ __launch_bounds__(128) void attn_kernel(float* __restrict__ out)
{
    extern __shared__ __half sm[];
    __half* kh = sm;
    __half* kl = kh + 128 * KVS;
    __half* vh = kl + 128 * KVS;

    const int t    = threadIdx.x;
    const int w    = t >> 5;
    const int lane = t & 31;
    const int g    = lane >> 2;
    const int tg   = lane & 3;
    const int j    = blockIdx.x & 7;
    const int b    = (blockIdx.x >> 3) & 63;
    const int half_ = blockIdx.x >> 9;
    const int qrow = (j * B_DIM + b) * H_DIM + half_ * 64;

    const uint32_t khb = smem_u32(kh), klb = smem_u32(kl);
    const uint32_t vhb = smem_u32(vh);

    // lane-invariant ldmatrix offsets (bytes)
    const uint32_t aofs  = (uint32_t)(((lane & 15) * KVS + ((lane >> 4) << 3)) * 2);
    const uint32_t kmofs = (uint32_t)((((lane & 7) + ((lane >> 4) << 3)) * KVS
                                       + (((lane >> 3) & 1) << 3)) * 2);
    const uint32_t vmofs = (uint32_t)((((lane & 7) + (((lane >> 3) & 1) << 3)) * KVS
                                       + ((lane >> 4) << 3)) * 2);

    // ---- stage Q (64 rows) into kh/kl, hoist A-frags to registers ----
#pragma unroll
    for (int p = 0; p < 8; p++) {
        int e = t + p * 128;            // 1024 uint4 tasks
        int arr = e >> 9;               // 0: hi, 1: lo
        int idx = e & 511;
        int row = idx >> 3;
        int ch  = idx & 7;
        const __half* src = arr ? g_Ql : g_Qh;
        __half* dst = arr ? kl : kh;
        *(uint4*)&dst[row * KVS + ch * 8] =
            *(const uint4*)&src[(size_t)(qrow + row) * HS + ch * 8];
    }
    __syncthreads();

    uint32_t qhf[4][4], qlf[4][4];
#pragma unroll
    for (int ks = 0; ks < 4; ks++) {
        uint32_t off = (uint32_t)((w * 16 * KVS + ks * 16) * 2);
        ldsm4(qhf[ks][0], qhf[ks][1], qhf[ks][2], qhf[ks][3], khb + off + aofs);
        ldsm4(qlf[ks][0], qlf[ks][1], qlf[ks][2], qlf[ks][3], klb + off + aofs);
    }

    float oacc[8][4];
#pragma unroll
    for (int nf = 0; nf < 8; nf++)
#pragma unroll
        for (int c = 0; c < 4; c++) oacc[nf][c] = 0.f;

    for (int i = 0; i < N_SEQ; i++) {
        __syncthreads();   // prev PV reads done (and Q-frag loads at i==0)
        const int kb0 = (i * B_DIM + b) * H_DIM;
        // copy K hi/lo + V hi: 3 x 1024 uint4 tasks
#pragma unroll 8
        for (int p = 0; p < 24; p++) {
            int e = t + p * 128;
            int arr = e >> 10;          // 0..2
            int idx = e & 1023;
            int row = idx >> 3;
            int ch  = idx & 7;
            const __half* src = (arr == 0) ? g_Kh : (arr == 1) ? g_Kl : g_Vh;
            __half* dst = (arr == 0) ? kh : (arr == 1) ? kl : vh;
            *(uint4*)&dst[row * KVS + ch * 8] =
                *(const uint4*)&src[(size_t)(kb0 + row) * HS + ch * 8];
        }
        __syncthreads();

        // ---- S = Q K^T : split-3, 16 rows x 128 keys in registers ----
        float sacc[16][4];
#pragma unroll
        for (int nf = 0; nf < 16; nf++)
#pragma unroll
            for (int c = 0; c < 4; c++) sacc[nf][c] = 0.f;

#pragma unroll
        for (int ks = 0; ks < 4; ks++) {
#pragma unroll
            for (int nfp = 0; nfp < 8; nfp++) {
                uint32_t off = (uint32_t)((nfp * 16 * KVS + ks * 16) * 2);
                uint32_t bh0, bh1, bh2, bh3, bl0, bl1, bl2, bl3;
                ldsm4(bh0, bh1, bh2, bh3, khb + off + kmofs);
                ldsm4(bl0, bl1, bl2, bl3, klb + off + kmofs);
                mma16816(sacc[2 * nfp],     qhf[ks], bh0, bh1);
                mma16816(sacc[2 * nfp],     qlf[ks], bh0, bh1);
                mma16816(sacc[2 * nfp],     qhf[ks], bl0, bl1);
                mma16816(sacc[2 * nfp + 1], qhf[ks], bh2, bh3);
                mma16816(sacc[2 * nfp + 1], qlf[ks], bh2, bh3);
                mma16816(sacc[2 * nfp + 1], qhf[ks], bl2, bl3);
            }
        }

        // ---- softmax in registers (rows g and g+8 of this warp's 16) ----
        float mx_a = sacc[0][0], mx_b = sacc[0][2];
#pragma unroll
        for (int nf = 0; nf < 16; nf++) {
            mx_a = fmaxf(mx_a, fmaxf(sacc[nf][0], sacc[nf][1]));
            mx_b = fmaxf(mx_b, fmaxf(sacc[nf][2], sacc[nf][3]));
        }
        mx_a = fmaxf(mx_a, __shfl_xor_sync(0xffffffffu, mx_a, 1));
        mx_a = fmaxf(mx_a, __shfl_xor_sync(0xffffffffu, mx_a, 2));
        mx_b = fmaxf(mx_b, __shfl_xor_sync(0xffffffffu, mx_b, 1));
        mx_b = fmaxf(mx_b, __shfl_xor_sync(0xffffffffu, mx_b, 2));
        float sum_a = 0.f, sum_b = 0.f;
#pragma unroll
        for (int nf = 0; nf < 16; nf++) {
            sacc[nf][0] = __expf(sacc[nf][0] - mx_a);
            sacc[nf][1] = __expf(sacc[nf][1] - mx_a);
            sacc[nf][2] = __expf(sacc[nf][2] - mx_b);
            sacc[nf][3] = __expf(sacc[nf][3] - mx_b);
            sum_a += sacc[nf][0] + sacc[nf][1];
            sum_b += sacc[nf][2] + sacc[nf][3];
        }
        sum_a += __shfl_xor_sync(0xffffffffu, sum_a, 1);
        sum_a += __shfl_xor_sync(0xffffffffu, sum_a, 2);
        sum_b += __shfl_xor_sync(0xffffffffu, sum_b, 1);
        sum_b += __shfl_xor_sync(0xffffffffu, sum_b, 2);
        const float inv_a = 1.0f / sum_a, inv_b = 1.0f / sum_b;

        // ---- pack P (fp16, single precision level) into A-fragments ----
        uint32_t pah[8][4];
#pragma unroll
        for (int s = 0; s < 8; s++) {
#pragma unroll
            for (int hf = 0; hf < 2; hf++) {
                int nf = 2 * s + hf;
                __half2 p01 = __floats2half2_rn(sacc[nf][0] * inv_a,
                                                sacc[nf][1] * inv_a);
                __half2 p23 = __floats2half2_rn(sacc[nf][2] * inv_b,
                                                sacc[nf][3] * inv_b);
                pah[s][2 * hf]     = *(uint32_t*)&p01;
                pah[s][2 * hf + 1] = *(uint32_t*)&p23;
            }
        }

        // ---- O += P V : SINGLE PASS (Ph·Vh), V via ldmatrix.trans ----
#pragma unroll
        for (int s = 0; s < 8; s++) {
#pragma unroll
            for (int nfp = 0; nfp < 4; nfp++) {
                uint32_t off = (uint32_t)((s * 16 * KVS + nfp * 16) * 2);
                uint32_t bh0, bh1, bh2, bh3;
                ldsm4t(bh0, bh1, bh2, bh3, vhb + off + vmofs);
                mma16816(oacc[2 * nfp],     pah[s], bh0, bh1);
                mma16816(oacc[2 * nfp + 1], pah[s], bh2, bh3);
            }
        }
    }

    // ---- write O ----
#pragma unroll
    for (int nf = 0; nf < 8; nf++) {
        size_t r0 = (size_t)(qrow + w * 16 + g) * HS + nf * 8 + 2 * tg;
        size_t r1 = (size_t)(qrow + w * 16 + g + 8) * HS + nf * 8 + 2 * tg;
        *(float2*)&out[r0] = make_float2(oacc[nf][0], oacc[nf][1]);
        *(float2*)&out[r1] = make_float2(oacc[nf][2], oacc[nf][3]);
    }
}

// ---------------------------------------------------------------------------
extern "C" void kernel_launch(void* const* d_in, const int* in_sizes, int n_in,
                              void* d_out, int out_size)
{
    const float* x  = (const float*)d_in[0];
    const float* Wq = (const float*)d_in[1];
    const float* Wk = (const float*)d_in[2];
    const float* Wv = (const float*)d_in[3];
    float* out = (float*)d_out;

    qkv_kernel<<<dim3(1024, 3), 256>>>(x, Wq, Wk, Wv);

    int smemB = 3 * 128 * KVS * (int)sizeof(__half);   // 55296
    cudaFuncSetAttribute(attn_kernel, cudaFuncAttributeMaxDynamicSharedMemorySize, smemB);
    attn_kernel<<<1024, 128, smemB>>>(out);
}